// round 16
// baseline (speedup 1.0000x reference)
#include <cuda_runtime.h>
#include <math.h>
#include <stdint.h>

#define BB 4
#define CH 128
#define HW 4096
#define LPOS (BB*HW)     // 16384 positions total
#define DINP 644
#define DI 256
#define NH 4
#define HD 64
#define DS 64
#define CC 384
#define Q 32             // SSD chunk length
#define NCHUNK (HW/Q)    // 128 chunks per (b)

typedef unsigned long long ull;

__device__ __forceinline__ float tf32r(float x) {
    uint32_t u;
    asm("cvt.rna.tf32.f32 %0, %1;" : "=r"(u) : "f"(x));
    return __uint_as_float(u);
}
__device__ __forceinline__ void mma_tf32(float* d, const uint32_t* a, const uint32_t* b) {
    asm("mma.sync.aligned.m16n8k8.row.col.f32.tf32.tf32.f32 "
        "{%0,%1,%2,%3},{%4,%5,%6,%7},{%8,%9},{%0,%1,%2,%3};"
        : "+f"(d[0]), "+f"(d[1]), "+f"(d[2]), "+f"(d[3])
        : "r"(a[0]), "r"(a[1]), "r"(a[2]), "r"(a[3]), "r"(b[0]), "r"(b[1]));
}

// ---------------- scratch (device globals; no allocation allowed) ----------
__device__ float g_normed[(size_t)LPOS*CH];          // 8.4 MB
__device__ float g_zx[(size_t)LPOS*DINP];            // 42 MB
__device__ float g_xbc[(size_t)LPOS*CC];             // 25 MB
__device__ float g_dt[(size_t)LPOS*NH];              // fp32-exact dt
__device__ float g_y[(size_t)LPOS*DI];               // 16.8 MB (intra-chunk y)
__device__ float g_U[(size_t)16*NCHUNK*HD*DS];       // 33.5 MB chunk outer sums [n][p]
__device__ float g_hst[(size_t)16*NCHUNK*HD*DS];     // 33.5 MB chunk start states [n][p]
__device__ float g_P[(size_t)16*HW];                 // exp(S_t) per (bh,pos)
__device__ float g_D[16*NCHUNK];                     // chunk decay
__device__ float g_gate[(size_t)LPOS*DI];            // 16.8 MB
__device__ float g_res[(size_t)LPOS*CH];             // 8.4 MB
__device__ float g_ff1[(size_t)LPOS*CH];             // 8.4 MB

// ---------------- 1. LayerNorm + fused fp32 dt (coalesced tile-transpose) -
__global__ void __launch_bounds__(256) ln_kernel(const float* __restrict__ noisy,
                          const float* __restrict__ gamma,
                          const float* __restrict__ beta,
                          const float* __restrict__ inw,
                          const float* __restrict__ dtb) {
    __shared__ float sD[128*33];
    __shared__ float sWdt[4][128];
    __shared__ float sG[128], sBe[128];
    int tid = threadIdx.x;
    for (int i = tid; i < 4*128; i += 256)
        sWdt[i >> 7][i & 127] = inw[(size_t)640*CH + i];
    if (tid < 128) { sG[tid] = gamma[tid]; sBe[tid] = beta[tid]; }

    int pos0 = blockIdx.x * 32;                 // multiple of 32, same batch
    int b = pos0 >> 12, sp0 = pos0 & 4095;
    const float* src = noisy + (size_t)b*CH*HW + sp0;
#pragma unroll
    for (int k = 0; k < 16; k++) {
        int idx = tid + k*256;                  // 4096 = 128ch x 32sp
        int ch = idx >> 5, spo = idx & 31;
        sD[ch*33 + spo] = src[(size_t)ch*HW + spo];
    }
    __syncthreads();

    int g = tid >> 3, sub = tid & 7;
    float vv[16];
    float s = 0.f, s2 = 0.f;
#pragma unroll
    for (int i = 0; i < 16; i++) {
        int ch = sub*16 + i;
        float v = sD[ch*33 + g];
        vv[i] = v; s += v; s2 += v*v;
    }
#pragma unroll
    for (int o = 4; o > 0; o >>= 1) {
        s  += __shfl_xor_sync(0xffffffffu, s,  o);
        s2 += __shfl_xor_sync(0xffffffffu, s2, o);
    }
    float mean = s * (1.f/128.f);
    float var  = s2 * (1.f/128.f) - mean*mean;
    float inv  = rsqrtf(var + 1e-5f);

    float dtp[4] = {0.f, 0.f, 0.f, 0.f};
#pragma unroll
    for (int i = 0; i < 16; i++) {
        int ch = sub*16 + i;
        float nv = (vv[i]-mean)*inv*sG[ch] + sBe[ch];
        sD[ch*33 + g] = nv;
#pragma unroll
        for (int h = 0; h < 4; h++) dtp[h] += nv*sWdt[h][ch];
    }
#pragma unroll
    for (int h = 0; h < 4; h++) {
        float d = dtp[h];
#pragma unroll
        for (int o = 4; o > 0; o >>= 1) d += __shfl_xor_sync(0xffffffffu, d, o);
        if (sub == 0) {
            float raw = d + dtb[h];
            g_dt[(size_t)(pos0+g)*NH + h] = (raw > 20.f) ? raw : log1pf(expf(raw));
        }
    }
    __syncthreads();

    float* dst = g_normed + (size_t)pos0*CH;
#pragma unroll
    for (int k = 0; k < 16; k++) {
        int idx = tid + k*256;
        int po = idx >> 7, ch = idx & 127;
        dst[(size_t)po*CH + ch] = sD[ch*33 + po];
    }
}

// ---------------- 2. in_proj GEMM via tf32 mma (reg double-buffered) ------
__global__ void __launch_bounds__(256) gemm_in_tc(const float* __restrict__ W) {
    __shared__ float sA[128*36];      // [m][k32] pad 36
    __shared__ float sW[32*136];      // [k][n128] pad 136
    int bm = blockIdx.y * 128, bn = blockIdx.x * 128;
    int tid = threadIdx.x;
    int wrp = tid >> 5, l = tid & 31;
    int lq = l >> 2, lr = l & 3;
    int mw = (wrp >> 1) * 32, nw = (wrp & 1) * 64;

    float4 pA[4], pW[4];
    auto prefetch = [&](int k0) {
#pragma unroll
        for (int v = 0; v < 4; v++) {
            int idx = tid + v*256;
            int m = idx >> 3, kq = idx & 7;
            pA[v] = *(const float4*)&g_normed[(size_t)(bm+m)*CH + k0 + kq*4];
        }
#pragma unroll
        for (int v = 0; v < 4; v++) {
            int idx = tid + v*256;
            int n = idx >> 3, kq = idx & 7;
            pW[v] = *(const float4*)&W[(size_t)(bn+n)*CH + k0 + kq*4];
        }
    };
    auto stage = [&]() {
#pragma unroll
        for (int v = 0; v < 4; v++) {
            int idx = tid + v*256;
            int m = idx >> 3, kq = idx & 7;
            float4 d = pA[v];
            d.x = tf32r(d.x); d.y = tf32r(d.y); d.z = tf32r(d.z); d.w = tf32r(d.w);
            *(float4*)&sA[m*36 + kq*4] = d;
        }
#pragma unroll
        for (int v = 0; v < 4; v++) {
            int idx = tid + v*256;
            int n = idx >> 3, kq = idx & 7;
            float4 d = pW[v];
            sW[(kq*4+0)*136 + n] = tf32r(d.x);
            sW[(kq*4+1)*136 + n] = tf32r(d.y);
            sW[(kq*4+2)*136 + n] = tf32r(d.z);
            sW[(kq*4+3)*136 + n] = tf32r(d.w);
        }
    };

    float acc[2][8][4];
#pragma unroll
    for (int mt = 0; mt < 2; mt++)
#pragma unroll
        for (int nt = 0; nt < 8; nt++)
#pragma unroll
            for (int i = 0; i < 4; i++) acc[mt][nt][i] = 0.f;

    prefetch(0);
    stage();
    __syncthreads();

    for (int it = 0; it < 4; it++) {
        if (it < 3) prefetch((it+1)*32);

#pragma unroll
        for (int ks = 0; ks < 4; ks++) {
            uint32_t a[2][4];
#pragma unroll
            for (int mt = 0; mt < 2; mt++) {
                int r0 = mw + mt*16 + lq;
                a[mt][0] = __float_as_uint(sA[r0*36 + ks*8 + lr]);
                a[mt][1] = __float_as_uint(sA[(r0+8)*36 + ks*8 + lr]);
                a[mt][2] = __float_as_uint(sA[r0*36 + ks*8 + lr + 4]);
                a[mt][3] = __float_as_uint(sA[(r0+8)*36 + ks*8 + lr + 4]);
            }
#pragma unroll
            for (int nt = 0; nt < 8; nt++) {
                uint32_t bb[2];
                bb[0] = __float_as_uint(sW[(ks*8+lr)*136 + nw + nt*8 + lq]);
                bb[1] = __float_as_uint(sW[(ks*8+lr+4)*136 + nw + nt*8 + lq]);
                mma_tf32(acc[0][nt], a[0], bb);
                mma_tf32(acc[1][nt], a[1], bb);
            }
        }
        if (it < 3) {
            __syncthreads();
            stage();
            __syncthreads();
        }
    }

#pragma unroll
    for (int mt = 0; mt < 2; mt++) {
        int row0 = bm + mw + mt*16 + lq;
#pragma unroll
        for (int nt = 0; nt < 8; nt++) {
            int col = bn + nw + nt*8 + lr*2;
            g_zx[(size_t)row0*DINP + col]       = acc[mt][nt][0];
            g_zx[(size_t)row0*DINP + col + 1]   = acc[mt][nt][1];
            g_zx[(size_t)(row0+8)*DINP + col]   = acc[mt][nt][2];
            g_zx[(size_t)(row0+8)*DINP + col+1] = acc[mt][nt][3];
        }
    }
}

// ---------------- 3. causal depthwise conv1d (k=5) + bias + SiLU ----------
__global__ void conv1d_kernel(const float* __restrict__ cw, const float* __restrict__ cb) {
    __shared__ float s[68][128];
    int b = blockIdx.z, ct = blockIdx.y * 128, p0 = blockIdx.x * 64;
    const float* zxb = g_zx + (size_t)b*HW*DINP;
    for (int idx = threadIdx.x; idx < 68*32; idx += 256) {
        int r = idx >> 5, c4 = idx & 31;
        int pos = p0 - 4 + r;
        float4 v = (pos >= 0) ? *(const float4*)&zxb[(size_t)pos*DINP + DI + ct + c4*4]
                              : make_float4(0.f, 0.f, 0.f, 0.f);
        *(float4*)&s[r][c4*4] = v;
    }
    __syncthreads();
    for (int idx = threadIdx.x; idx < 64*128; idx += 256) {
        int r = idx >> 7, c = idx & 127;
        int ch = ct + c;
        float acc = cb[ch];
#pragma unroll
        for (int k = 0; k < 5; k++) acc += s[r+k][c] * cw[ch*5 + k];
        float o = acc / (1.f + expf(-acc));
        g_xbc[((size_t)b*HW + p0 + r)*CC + ch] = o;
    }
}

// ---------------- 4a. SSD chunk kernel — tensor-core GEMMs (U^T form) -----
__global__ void __launch_bounds__(256) ssd_chunk(const float* __restrict__ Alog) {
    __shared__ float sX [Q*72];     // [s][p]  32x64 B-frag (stride 72)
    __shared__ float sBt[64*40];    // [n][s]  64x32; B-frag for M, A-frag for U^T
    __shared__ float sC [Q*68];     // [t][n]  32x64 A-frag for M
    __shared__ float sMw[Q*36];     // [t][s]  32x32 A-frag for y
    __shared__ float sdt[Q], sS[Q], sWU[Q];

    int bid = blockIdx.x;
    int c  = bid & 127;
    int h  = (bid >> 7) & 3;
    int b  = bid >> 9;
    int bh = b*4 + h;
    int pos0 = b*HW + c*Q;
    int tid = threadIdx.x;
    int wrp = tid >> 5, l = tid & 31;
    int lq = l >> 2, lr = l & 3;

#pragma unroll
    for (int v = 0; v < 2; v++) {
        int idx = tid + v*256;
        int s = idx >> 4, n0 = (idx & 15)*4;
        const float* row = g_xbc + (size_t)(pos0+s)*CC;
        float4 xv = *(const float4*)&row[h*HD + n0];
        float4 bv = *(const float4*)&row[DI + n0];
        float4 cv = *(const float4*)&row[DI + DS + n0];
        xv.x = tf32r(xv.x); xv.y = tf32r(xv.y); xv.z = tf32r(xv.z); xv.w = tf32r(xv.w);
        cv.x = tf32r(cv.x); cv.y = tf32r(cv.y); cv.z = tf32r(cv.z); cv.w = tf32r(cv.w);
        *(float4*)&sX[s*72 + n0] = xv;
        *(float4*)&sC[s*68 + n0] = cv;
        sBt[(n0+0)*40 + s] = tf32r(bv.x);
        sBt[(n0+1)*40 + s] = tf32r(bv.y);
        sBt[(n0+2)*40 + s] = tf32r(bv.z);
        sBt[(n0+3)*40 + s] = tf32r(bv.w);
    }
    // warp 0: dt load + parallel prefix scan + wU/P/D
    if (tid < 32) {
        float dtv = g_dt[(size_t)(pos0+tid)*NH + h];
        sdt[tid] = dtv;
        float Ah = -expf(Alog[h]);
        float v = dtv * Ah;
#pragma unroll
        for (int o = 1; o < 32; o <<= 1) {
            float nv = __shfl_up_sync(0xffffffffu, v, o);
            if (tid >= o) v += nv;
        }
        sS[tid] = v;
        float Stot = __shfl_sync(0xffffffffu, v, 31);
        sWU[tid] = expf(Stot - v) * dtv;
        g_P[(size_t)bh*HW + c*Q + tid] = expf(v);
        if (tid == 31) g_D[bh*NCHUNK + c] = expf(Stot);
    }
    __syncthreads();

    // Phase M
    {
        int mt = wrp >> 2, st = wrp & 3;
        float d[4] = {0.f, 0.f, 0.f, 0.f};
#pragma unroll
        for (int ks = 0; ks < 8; ks++) {
            uint32_t a[4], bbr[2];
            const float* Ab = &sC[(mt*16 + lq)*68 + ks*8];
            a[0] = __float_as_uint(Ab[lr]);
            a[1] = __float_as_uint(Ab[8*68 + lr]);
            a[2] = __float_as_uint(Ab[lr + 4]);
            a[3] = __float_as_uint(Ab[8*68 + lr + 4]);
            bbr[0] = __float_as_uint(sBt[(ks*8 + lr)*40 + st*8 + lq]);
            bbr[1] = __float_as_uint(sBt[(ks*8 + lr + 4)*40 + st*8 + lq]);
            mma_tf32(d, a, bbr);
        }
        int t0 = mt*16 + lq, s0 = st*8 + lr*2;
        float st0 = sS[t0], st8 = sS[t0+8];
        float ss0 = sS[s0], ss1 = sS[s0+1];
        float dt0 = sdt[s0], dt1 = sdt[s0+1];
        sMw[t0*36 + s0]       = tf32r((s0   <= t0  ) ? d[0]*expf(st0 - ss0)*dt0 : 0.f);
        sMw[t0*36 + s0+1]     = tf32r((s0+1 <= t0  ) ? d[1]*expf(st0 - ss1)*dt1 : 0.f);
        sMw[(t0+8)*36 + s0]   = tf32r((s0   <= t0+8) ? d[2]*expf(st8 - ss0)*dt0 : 0.f);
        sMw[(t0+8)*36 + s0+1] = tf32r((s0+1 <= t0+8) ? d[3]*expf(st8 - ss1)*dt1 : 0.f);
    }
    __syncthreads();

    // Scale sBt columns by wU[s]
#pragma unroll
    for (int v = 0; v < 2; v++) {
        int idx = tid + v*256;
        int n = idx >> 3, s0 = (idx & 7)*4;
        float4 d = *(const float4*)&sBt[n*40 + s0];
        float4 wu = *(const float4*)&sWU[s0];
        d.x = tf32r(d.x*wu.x); d.y = tf32r(d.y*wu.y);
        d.z = tf32r(d.z*wu.z); d.w = tf32r(d.w*wu.w);
        *(float4*)&sBt[n*40 + s0] = d;
    }
    __syncthreads();

    // Phase y_intra then U^T back-to-back
    {
        float dy[2][4];
#pragma unroll
        for (int mt = 0; mt < 2; mt++)
#pragma unroll
            for (int i = 0; i < 4; i++) dy[mt][i] = 0.f;
#pragma unroll
        for (int ks = 0; ks < 4; ks++) {
            uint32_t bbr[2];
            bbr[0] = __float_as_uint(sX[(ks*8 + lr)*72 + wrp*8 + lq]);
            bbr[1] = __float_as_uint(sX[(ks*8 + lr + 4)*72 + wrp*8 + lq]);
#pragma unroll
            for (int mt = 0; mt < 2; mt++) {
                uint32_t a[4];
                const float* Ab = &sMw[(mt*16 + lq)*36 + ks*8];
                a[0] = __float_as_uint(Ab[lr]);
                a[1] = __float_as_uint(Ab[8*36 + lr]);
                a[2] = __float_as_uint(Ab[lr + 4]);
                a[3] = __float_as_uint(Ab[8*36 + lr + 4]);
                mma_tf32(dy[mt], a, bbr);
            }
        }
        int p0 = wrp*8 + lr*2;
#pragma unroll
        for (int mt = 0; mt < 2; mt++) {
            int t0 = mt*16 + lq;
            float2 v0; v0.x = dy[mt][0]; v0.y = dy[mt][1];
            float2 v1; v1.x = dy[mt][2]; v1.y = dy[mt][3];
            *(float2*)&g_y[(size_t)(pos0 + t0)*DI + h*HD + p0]     = v0;
            *(float2*)&g_y[(size_t)(pos0 + t0 + 8)*DI + h*HD + p0] = v1;
        }
    }
    {
        float du[4][4];
#pragma unroll
        for (int mt = 0; mt < 4; mt++)
#pragma unroll
            for (int i = 0; i < 4; i++) du[mt][i] = 0.f;
#pragma unroll
        for (int ks = 0; ks < 4; ks++) {
            uint32_t bbr[2];
            bbr[0] = __float_as_uint(sX[(ks*8 + lr)*72 + wrp*8 + lq]);
            bbr[1] = __float_as_uint(sX[(ks*8 + lr + 4)*72 + wrp*8 + lq]);
#pragma unroll
            for (int mt = 0; mt < 4; mt++) {
                uint32_t a[4];
                const float* Ab = &sBt[(mt*16 + lq)*40 + ks*8];
                a[0] = __float_as_uint(Ab[lr]);
                a[1] = __float_as_uint(Ab[8*40 + lr]);
                a[2] = __float_as_uint(Ab[lr + 4]);
                a[3] = __float_as_uint(Ab[8*40 + lr + 4]);
                mma_tf32(du[mt], a, bbr);
            }
        }
        float* Uo = g_U + ((size_t)bh*NCHUNK + c)*HD*DS;   // [n][p]
        int p0 = wrp*8 + lr*2;
#pragma unroll
        for (int mt = 0; mt < 4; mt++) {
            int n0 = mt*16 + lq;
            float2 v0; v0.x = du[mt][0]; v0.y = du[mt][1];
            float2 v1; v1.x = du[mt][2]; v1.y = du[mt][3];
            *(float2*)&Uo[n0*64 + p0]       = v0;
            *(float2*)&Uo[(n0+8)*64 + p0]   = v1;
        }
    }
}

// ---------------- 4b. chunk-state recurrence (4-deep prefetch) ------------
__global__ void ssd_chain() {
    int e = blockIdx.x*256 + threadIdx.x;
    int bh = e >> 12, el = e & 4095;
    const float* U = g_U   + (size_t)bh*NCHUNK*4096 + el;
    float*       H = g_hst + (size_t)bh*NCHUNK*4096 + el;
    const float* Dd = g_D + bh*NCHUNK;
    float u[4];
    u[0] = U[0];
    u[1] = U[(size_t)1*4096];
    u[2] = U[(size_t)2*4096];
    u[3] = U[(size_t)3*4096];
    float hval = 0.f;
    for (int ci = 0; ci < NCHUNK; ci++) {
        float uc = u[ci & 3];
        if (ci + 4 < NCHUNK) u[ci & 3] = U[(size_t)(ci+4)*4096];
        H[(size_t)ci*4096] = hval;
        hval = Dd[ci]*hval + uc;
    }
}

// ---------------- 4c. FUSED inter-chunk output + D-skip + gate + RMSNorm --
// Grid (b, chunk) = 512 blocks. Loops h=0..3 (dy kept in registers), then
// redistributes via smem union and applies the gate inline. Arithmetic order
// identical to the previous split kernels: (intra + dy) + D*x.
__global__ void __launch_bounds__(256) ssd_ig(const float* __restrict__ Dsk,
                                              const float* __restrict__ rmsw) {
    __shared__ float sPool[8448];   // max(64*72 + 32*68 = 6784, 32*264 = 8448)
    float* sHt = sPool;             // [n][p] 64x64 B-frag (stride 72)
    float* sCw = sPool + 64*72;     // [t][n] 32x64 A-frag (stride 68)
    float* sY  = sPool;             // phase 2: [t][ch] 32x256 (stride 264)

    int bid = blockIdx.x;
    int c = bid & 127, b = bid >> 7;
    int pos0 = b*HW + c*Q;
    int tid = threadIdx.x;
    int wrp = tid >> 5, l = tid & 31;
    int lq = l >> 2, lr = l & 3;

    float dyAll[4][8];

    for (int h = 0; h < 4; h++) {
        int bh = b*4 + h;
        const float* Hsrc = g_hst + ((size_t)bh*NCHUNK + c)*HD*DS;  // [n][p]
#pragma unroll
        for (int v = 0; v < 4; v++) {
            int idx = tid + v*256;
            int n = idx >> 4, p0 = (idx & 15)*4;
            float4 hv = *(const float4*)&Hsrc[n*64 + p0];
            hv.x = tf32r(hv.x); hv.y = tf32r(hv.y);
            hv.z = tf32r(hv.z); hv.w = tf32r(hv.w);
            *(float4*)&sHt[n*72 + p0] = hv;
        }
#pragma unroll
        for (int v = 0; v < 2; v++) {
            int idx = tid + v*256;
            int t = idx >> 4, n0 = (idx & 15)*4;
            float4 cv = *(const float4*)&g_xbc[(size_t)(pos0+t)*CC + DI + DS + n0];
            float pt = g_P[(size_t)bh*HW + c*Q + t];
            cv.x = tf32r(cv.x*pt); cv.y = tf32r(cv.y*pt);
            cv.z = tf32r(cv.z*pt); cv.w = tf32r(cv.w*pt);
            *(float4*)&sCw[t*68 + n0] = cv;
        }
        __syncthreads();

        float dy[2][4];
#pragma unroll
        for (int mt = 0; mt < 2; mt++)
#pragma unroll
            for (int i = 0; i < 4; i++) dy[mt][i] = 0.f;
#pragma unroll
        for (int ks = 0; ks < 8; ks++) {
            uint32_t bbr[2];
            bbr[0] = __float_as_uint(sHt[(ks*8 + lr)*72 + wrp*8 + lq]);
            bbr[1] = __float_as_uint(sHt[(ks*8 + lr + 4)*72 + wrp*8 + lq]);
#pragma unroll
            for (int mt = 0; mt < 2; mt++) {
                uint32_t a[4];
                const float* Ab = &sCw[(mt*16 + lq)*68 + ks*8];
                a[0] = __float_as_uint(Ab[lr]);
                a[1] = __float_as_uint(Ab[8*68 + lr]);
                a[2] = __float_as_uint(Ab[lr + 4]);
                a[3] = __float_as_uint(Ab[8*68 + lr + 4]);
                mma_tf32(dy[mt], a, bbr);
            }
        }
#pragma unroll
        for (int mt = 0; mt < 2; mt++)
#pragma unroll
            for (int i = 0; i < 4; i++) dyAll[h][mt*4 + i] = dy[mt][i];
        __syncthreads();            // done reading sHt/sCw before next h (or sY)
    }

    // redistribute dy through sY (overlays sHt/sCw)
    {
        int p0 = wrp*8 + lr*2;
#pragma unroll
        for (int h = 0; h < 4; h++)
#pragma unroll
            for (int mt = 0; mt < 2; mt++) {
                int t0 = mt*16 + lq;
                float2 v0; v0.x = dyAll[h][mt*4+0]; v0.y = dyAll[h][mt*4+1];
                float2 v1; v1.x = dyAll[h][mt*4+2]; v1.y = dyAll[h][mt*4+3];
                *(float2*)&sY[t0*264 + h*64 + p0]     = v0;
                *(float2*)&sY[(t0+8)*264 + h*64 + p0] = v1;
            }
    }
    __syncthreads();

    // phase 2: gate. 8 threads per position, 32 channels each.
    int g = tid >> 3, sub = tid & 7;
    int pos = pos0 + g;
    const float4* yrow = (const float4*)(g_y   + (size_t)pos*DI);
    const float4* zrow = (const float4*)(g_zx  + (size_t)pos*DINP);
    const float4* xrow = (const float4*)(g_xbc + (size_t)pos*CC);
    float4 gv[8]; float ss = 0.f;
#pragma unroll
    for (int i = 0; i < 8; i++) {
        int q = sub*8 + i;                  // float4 index 0..63
        int h = q >> 4;
        float Dh = Dsk[h];
        float4 yv = yrow[q];
        float4 dv = *(const float4*)&sY[g*264 + q*4];
        yv.x += dv.x; yv.y += dv.y; yv.z += dv.z; yv.w += dv.w;
        float4 xv = xrow[q], zv = zrow[q];
        float4 gg;
        gg.x = (yv.x + Dh*xv.x) * (zv.x / (1.f + expf(-zv.x)));
        gg.y = (yv.y + Dh*xv.y) * (zv.y / (1.f + expf(-zv.y)));
        gg.z = (yv.z + Dh*xv.z) * (zv.z / (1.f + expf(-zv.z)));
        gg.w = (yv.w + Dh*xv.w) * (zv.w / (1.f + expf(-zv.w)));
        gv[i] = gg;
        ss += gg.x*gg.x + gg.y*gg.y + gg.z*gg.z + gg.w*gg.w;
    }
#pragma unroll
    for (int o = 4; o > 0; o >>= 1) ss += __shfl_xor_sync(0xffffffffu, ss, o);
    float sc = rsqrtf(ss*(1.f/256.f) + 1e-5f);
    float4* grow = (float4*)(g_gate + (size_t)pos*DI);
#pragma unroll
    for (int i = 0; i < 8; i++) {
        int q = sub*8 + i;
        const float4 rw = *(const float4*)&rmsw[q*4];
        float4 gg = gv[i];
        gg.x *= sc*rw.x; gg.y *= sc*rw.y; gg.z *= sc*rw.z; gg.w *= sc*rw.w;
        grow[q] = gg;
    }
}

// ---------------- 6. out_proj GEMM (reg double-buffered) + residual -------
__global__ void __launch_bounds__(256) gemm_out_tc(const float* __restrict__ W,
                                                   const float* __restrict__ noisy) {
    __shared__ float sA[128*36];
    __shared__ float sW[32*136];
    int bm = blockIdx.x * 128;
    int tid = threadIdx.x;
    int wrp = tid >> 5, l = tid & 31;
    int lq = l >> 2, lr = l & 3;
    int mw = (wrp >> 1) * 32, nw = (wrp & 1) * 64;

    float4 pA[4], pW[4];
    auto prefetch = [&](int k0) {
#pragma unroll
        for (int v = 0; v < 4; v++) {
            int idx = tid + v*256;
            int m = idx >> 3, kq = idx & 7;
            pA[v] = *(const float4*)&g_gate[(size_t)(bm+m)*DI + k0 + kq*4];
        }
#pragma unroll
        for (int v = 0; v < 4; v++) {
            int idx = tid + v*256;
            int n = idx >> 3, kq = idx & 7;
            pW[v] = *(const float4*)&W[(size_t)n*DI + k0 + kq*4];
        }
    };
    auto stage = [&]() {
#pragma unroll
        for (int v = 0; v < 4; v++) {
            int idx = tid + v*256;
            int m = idx >> 3, kq = idx & 7;
            float4 d = pA[v];
            d.x = tf32r(d.x); d.y = tf32r(d.y); d.z = tf32r(d.z); d.w = tf32r(d.w);
            *(float4*)&sA[m*36 + kq*4] = d;
        }
#pragma unroll
        for (int v = 0; v < 4; v++) {
            int idx = tid + v*256;
            int n = idx >> 3, kq = idx & 7;
            float4 d = pW[v];
            sW[(kq*4+0)*136 + n] = tf32r(d.x);
            sW[(kq*4+1)*136 + n] = tf32r(d.y);
            sW[(kq*4+2)*136 + n] = tf32r(d.z);
            sW[(kq*4+3)*136 + n] = tf32r(d.w);
        }
    };

    float acc[2][8][4];
#pragma unroll
    for (int mt = 0; mt < 2; mt++)
#pragma unroll
        for (int nt = 0; nt < 8; nt++)
#pragma unroll
            for (int i = 0; i < 4; i++) acc[mt][nt][i] = 0.f;

    prefetch(0);
    stage();
    __syncthreads();

    for (int it = 0; it < 8; it++) {
        if (it < 7) prefetch((it+1)*32);

#pragma unroll
        for (int ks = 0; ks < 4; ks++) {
            uint32_t a[2][4];
#pragma unroll
            for (int mt = 0; mt < 2; mt++) {
                int r0 = mw + mt*16 + lq;
                a[mt][0] = __float_as_uint(sA[r0*36 + ks*8 + lr]);
                a[mt][1] = __float_as_uint(sA[(r0+8)*36 + ks*8 + lr]);
                a[mt][2] = __float_as_uint(sA[r0*36 + ks*8 + lr + 4]);
                a[mt][3] = __float_as_uint(sA[(r0+8)*36 + ks*8 + lr + 4]);
            }
#pragma unroll
            for (int nt = 0; nt < 8; nt++) {
                uint32_t bb[2];
                bb[0] = __float_as_uint(sW[(ks*8+lr)*136 + nw + nt*8 + lq]);
                bb[1] = __float_as_uint(sW[(ks*8+lr+4)*136 + nw + nt*8 + lq]);
                mma_tf32(acc[0][nt], a[0], bb);
                mma_tf32(acc[1][nt], a[1], bb);
            }
        }
        if (it < 7) {
            __syncthreads();
            stage();
            __syncthreads();
        }
    }

    // 4-pass m-group transpose epilogue: coalesced (b,c,sp) stores
    float* sT = sA;
    int b = bm >> 12, sp0 = bm & 4095;
    for (int mg = 0; mg < 4; mg++) {
        __syncthreads();
        if ((wrp >> 1) == mg) {
#pragma unroll
            for (int mt = 0; mt < 2; mt++)
#pragma unroll
                for (int nt = 0; nt < 8; nt++) {
                    int cl = nw + nt*8 + lr*2;
                    sT[cl*33 + mt*16 + lq]         = acc[mt][nt][0];
                    sT[(cl+1)*33 + mt*16 + lq]     = acc[mt][nt][1];
                    sT[cl*33 + mt*16 + lq + 8]     = acc[mt][nt][2];
                    sT[(cl+1)*33 + mt*16 + lq + 8] = acc[mt][nt][3];
                }
        }
        __syncthreads();
#pragma unroll
        for (int r = 0; r < 16; r++) {
            int lin = tid + r*256;
            int cch = lin >> 5, mm = lin & 31;
            size_t o = ((size_t)(b*CH + cch))*HW + sp0 + mg*32 + mm;
            g_res[o] = noisy[o] + sT[cch*33 + mm];
        }
    }
}

// ---------------- 7/8. 3x3 conv via tf32 mma, register double-buffer ------
__global__ void __launch_bounds__(256) conv3_tc(const float* __restrict__ in,
                                                const float* __restrict__ w,
                                                const float* __restrict__ bias,
                                                float* __restrict__ out,
                                                const float* __restrict__ resid) {
    __shared__ float sT[6*66*12];     // [r][xx][ci8] pad 12
    __shared__ float sW[9*8*72];      // [tap][ci8][co64 pad 72]

    int b = blockIdx.z, coh = blockIdx.x * 64, y0 = blockIdx.y * 4;
    int tid = threadIdx.x;
    int wrp = tid >> 5, l = tid & 31;
    int yl = wrp >> 1, xh = wrp & 1;
    int lq = l >> 2, lr = l & 3;

    float rIn[13], rW[18];

    auto load_regs = [&](int cc) {
        int ci0 = cc * 8;
#pragma unroll
        for (int k = 0; k < 13; k++) {
            int idx = tid + k*256;
            if (idx < 3168) {
                int xx = idx % 66;
                int t2 = idx / 66;
                int ci = t2 & 7, r = t2 >> 3;
                int iy = y0 - 1 + r; iy = iy < 0 ? -iy : (iy >= 64 ? 126 - iy : iy);
                int ix = xx - 1;     ix = ix < 0 ? -ix : (ix >= 64 ? 126 - ix : ix);
                rIn[k] = in[(((size_t)b*CH + ci0 + ci)*64 + iy)*64 + ix];
            }
        }
#pragma unroll
        for (int k = 0; k < 18; k++) {
            int idx = tid + k*256;
            int co = idx / 72;
            int rem = idx - co*72;
            int ci = rem / 9, kk = rem - ci*9;
            rW[k] = w[((size_t)(coh+co)*CH + ci0 + ci)*9 + kk];
        }
    };
    auto store_regs = [&]() {
#pragma unroll
        for (int k = 0; k < 13; k++) {
            int idx = tid + k*256;
            if (idx < 3168) {
                int xx = idx % 66;
                int t2 = idx / 66;
                int ci = t2 & 7, r = t2 >> 3;
                sT[(r*66 + xx)*12 + ci] = tf32r(rIn[k]);
            }
        }
#pragma unroll
        for (int k = 0; k < 18; k++) {
            int idx = tid + k*256;
            int co = idx / 72;
            int rem = idx - co*72;
            int ci = rem / 9, kk = rem - ci*9;
            sW[(kk*8 + ci)*72 + co] = tf32r(rW[k]);
        }
    };

    float acc[2][8][4];
#pragma unroll
    for (int mt = 0; mt < 2; mt++)
#pragma unroll
        for (int nt = 0; nt < 8; nt++)
#pragma unroll
            for (int i = 0; i < 4; i++) acc[mt][nt][i] = 0.f;

    load_regs(0);
    store_regs();
    __syncthreads();

    for (int cc = 0; cc < 16; cc++) {
        if (cc < 15) load_regs(cc + 1);

#pragma unroll
        for (int kk = 0; kk < 9; kk++) {
            int ky = kk / 3, kx = kk - ky*3;
            uint32_t a[2][4];
#pragma unroll
            for (int mt = 0; mt < 2; mt++) {
                const float* Tb = &sT[((yl + ky)*66 + xh*32 + mt*16 + kx)*12];
                a[mt][0] = __float_as_uint(Tb[lq*12 + lr]);
                a[mt][1] = __float_as_uint(Tb[(lq+8)*12 + lr]);
                a[mt][2] = __float_as_uint(Tb[lq*12 + lr + 4]);
                a[mt][3] = __float_as_uint(Tb[(lq+8)*12 + lr + 4]);
            }
            const float* Wb = &sW[kk*8*72];
#pragma unroll
            for (int nt = 0; nt < 8; nt++) {
                uint32_t bb[2];
                bb[0] = __float_as_uint(Wb[lr*72 + nt*8 + lq]);
                bb[1] = __float_as_uint(Wb[(lr+4)*72 + nt*8 + lq]);
                mma_tf32(acc[0][nt], a[0], bb);
                mma_tf32(acc[1][nt], a[1], bb);
            }
        }
        __syncthreads();
        if (cc < 15) {
            store_regs();
            __syncthreads();
        }
    }

    int y = y0 + yl;
#pragma unroll
    for (int mt = 0; mt < 2; mt++) {
        int x = xh*32 + mt*16 + lq;
#pragma unroll
        for (int nt = 0; nt < 8; nt++) {
            int co = coh + nt*8 + lr*2;
            float b0 = bias[co], b1 = bias[co+1];
            size_t o0 = (((size_t)b*CH + co  )*64 + y)*64 + x;
            size_t o1 = (((size_t)b*CH + co+1)*64 + y)*64 + x;
            float v0 = fmaxf(acc[mt][nt][0] + b0, 0.f);
            float v1 = fmaxf(acc[mt][nt][1] + b1, 0.f);
            float v2 = fmaxf(acc[mt][nt][2] + b0, 0.f);
            float v3 = fmaxf(acc[mt][nt][3] + b1, 0.f);
            if (resid) {
                v0 += resid[o0]; v1 += resid[o1];
                v2 += resid[o0 + 8]; v3 += resid[o1 + 8];
            }
            out[o0] = v0; out[o1] = v1;
            out[o0 + 8] = v2; out[o1 + 8] = v3;
        }
    }
}

// ---------------- launch ---------------------------------------------------
extern "C" void kernel_launch(void* const* d_in, const int* in_sizes, int n_in,
                              void* d_out, int out_size) {
    const float* noisy = (const float*)d_in[0];
    const float* aux   = (const float*)d_in[1];
    const float* gamma = (const float*)d_in[2];
    const float* beta  = (const float*)d_in[3];
    const float* inw   = (const float*)d_in[4];
    const float* cw    = (const float*)d_in[5];
    const float* cb    = (const float*)d_in[6];
    const float* alog  = (const float*)d_in[7];
    const float* dtb   = (const float*)d_in[8];
    const float* Dsk   = (const float*)d_in[9];
    const float* rmsw  = (const float*)d_in[10];
    const float* outw  = (const float*)d_in[11];
    const float* fw1   = (const float*)d_in[12];
    const float* fb1   = (const float*)d_in[13];
    const float* fw2   = (const float*)d_in[14];
    const float* fb2   = (const float*)d_in[15];
    float* out = (float*)d_out;

    void *p_res, *p_ff1;
    cudaGetSymbolAddress(&p_res, g_res);
    cudaGetSymbolAddress(&p_ff1, g_ff1);

    ln_kernel<<<512, 256>>>(noisy, gamma, beta, inw, dtb);
    gemm_in_tc<<<dim3(5, 128), 256>>>(inw);
    conv1d_kernel<<<dim3(64, 3, 4), 256>>>(cw, cb);
    ssd_chunk<<<2048, 256>>>(alog);
    ssd_chain<<<256, 256>>>();
    ssd_ig<<<512, 256>>>(Dsk, rmsw);
    gemm_out_tc<<<128, 256>>>(outw, noisy);
    conv3_tc<<<dim3(2, 16, 4), 256>>>((const float*)p_res, fw1, fb1, (float*)p_ff1, nullptr);
    conv3_tc<<<dim3(2, 16, 4), 256>>>((const float*)p_ff1, fw2, fb2, out, (const float*)p_res);

    // aux passthrough: second half of output
    if (out_size >= 2*LPOS*CH) {
        cudaMemcpyAsync(out + (size_t)LPOS*CH, aux, (size_t)LPOS*CH*sizeof(float),
                        cudaMemcpyDeviceToDevice, 0);
    }
}

// round 17
// speedup vs baseline: 1.0682x; 1.0682x over previous
#include <cuda_runtime.h>
#include <math.h>
#include <stdint.h>

#define BB 4
#define CH 128
#define HW 4096
#define LPOS (BB*HW)     // 16384 positions total
#define DINP 644
#define DI 256
#define NH 4
#define HD 64
#define DS 64
#define CC 384
#define Q 32             // SSD chunk length
#define NCHUNK (HW/Q)    // 128 chunks per (b)

typedef unsigned long long ull;

__device__ __forceinline__ float tf32r(float x) {
    uint32_t u;
    asm("cvt.rna.tf32.f32 %0, %1;" : "=r"(u) : "f"(x));
    return __uint_as_float(u);
}
__device__ __forceinline__ void mma_tf32(float* d, const uint32_t* a, const uint32_t* b) {
    asm("mma.sync.aligned.m16n8k8.row.col.f32.tf32.tf32.f32 "
        "{%0,%1,%2,%3},{%4,%5,%6,%7},{%8,%9},{%0,%1,%2,%3};"
        : "+f"(d[0]), "+f"(d[1]), "+f"(d[2]), "+f"(d[3])
        : "r"(a[0]), "r"(a[1]), "r"(a[2]), "r"(a[3]), "r"(b[0]), "r"(b[1]));
}

// ---------------- scratch (device globals; no allocation allowed) ----------
__device__ float g_normed[(size_t)LPOS*CH];          // 8.4 MB
__device__ float g_zx[(size_t)LPOS*DINP];            // 42 MB
__device__ float g_xbc[(size_t)LPOS*CC];             // 25 MB
__device__ float g_dt[(size_t)LPOS*NH];              // fp32-exact dt
__device__ float g_y[(size_t)LPOS*DI];               // 16.8 MB (intra-chunk y)
__device__ float g_U[(size_t)16*NCHUNK*HD*DS];       // 33.5 MB chunk outer sums [n][p]
__device__ float g_hst[(size_t)16*NCHUNK*HD*DS];     // 33.5 MB chunk start states [n][p]
__device__ float g_P[(size_t)16*HW];                 // exp(S_t) per (bh,pos)
__device__ float g_D[16*NCHUNK];                     // chunk decay
__device__ float g_gate[(size_t)LPOS*DI];            // 16.8 MB
__device__ float g_res[(size_t)LPOS*CH];             // 8.4 MB
__device__ float g_ff1[(size_t)LPOS*CH];             // 8.4 MB

// ---------------- 1. LayerNorm + fused fp32 dt (coalesced tile-transpose) -
__global__ void __launch_bounds__(256) ln_kernel(const float* __restrict__ noisy,
                          const float* __restrict__ gamma,
                          const float* __restrict__ beta,
                          const float* __restrict__ inw,
                          const float* __restrict__ dtb) {
    __shared__ float sD[128*33];
    __shared__ float sWdt[4][128];
    __shared__ float sG[128], sBe[128];
    int tid = threadIdx.x;
    for (int i = tid; i < 4*128; i += 256)
        sWdt[i >> 7][i & 127] = inw[(size_t)640*CH + i];
    if (tid < 128) { sG[tid] = gamma[tid]; sBe[tid] = beta[tid]; }

    int pos0 = blockIdx.x * 32;                 // multiple of 32, same batch
    int b = pos0 >> 12, sp0 = pos0 & 4095;
    const float* src = noisy + (size_t)b*CH*HW + sp0;
#pragma unroll
    for (int k = 0; k < 16; k++) {
        int idx = tid + k*256;                  // 4096 = 128ch x 32sp
        int ch = idx >> 5, spo = idx & 31;
        sD[ch*33 + spo] = src[(size_t)ch*HW + spo];
    }
    __syncthreads();

    int g = tid >> 3, sub = tid & 7;
    float vv[16];
    float s = 0.f, s2 = 0.f;
#pragma unroll
    for (int i = 0; i < 16; i++) {
        int ch = sub*16 + i;
        float v = sD[ch*33 + g];
        vv[i] = v; s += v; s2 += v*v;
    }
#pragma unroll
    for (int o = 4; o > 0; o >>= 1) {
        s  += __shfl_xor_sync(0xffffffffu, s,  o);
        s2 += __shfl_xor_sync(0xffffffffu, s2, o);
    }
    float mean = s * (1.f/128.f);
    float var  = s2 * (1.f/128.f) - mean*mean;
    float inv  = rsqrtf(var + 1e-5f);

    float dtp[4] = {0.f, 0.f, 0.f, 0.f};
#pragma unroll
    for (int i = 0; i < 16; i++) {
        int ch = sub*16 + i;
        float nv = (vv[i]-mean)*inv*sG[ch] + sBe[ch];
        sD[ch*33 + g] = nv;
#pragma unroll
        for (int h = 0; h < 4; h++) dtp[h] += nv*sWdt[h][ch];
    }
#pragma unroll
    for (int h = 0; h < 4; h++) {
        float d = dtp[h];
#pragma unroll
        for (int o = 4; o > 0; o >>= 1) d += __shfl_xor_sync(0xffffffffu, d, o);
        if (sub == 0) {
            float raw = d + dtb[h];
            g_dt[(size_t)(pos0+g)*NH + h] = (raw > 20.f) ? raw : log1pf(expf(raw));
        }
    }
    __syncthreads();

    float* dst = g_normed + (size_t)pos0*CH;
#pragma unroll
    for (int k = 0; k < 16; k++) {
        int idx = tid + k*256;
        int po = idx >> 7, ch = idx & 127;
        dst[(size_t)po*CH + ch] = sD[ch*33 + po];
    }
}

// ---------------- 2. in_proj GEMM via tf32 mma (reg double-buffered) ------
__global__ void __launch_bounds__(256) gemm_in_tc(const float* __restrict__ W) {
    __shared__ float sA[128*36];      // [m][k32] pad 36
    __shared__ float sW[32*136];      // [k][n128] pad 136
    int bm = blockIdx.y * 128, bn = blockIdx.x * 128;
    int tid = threadIdx.x;
    int wrp = tid >> 5, l = tid & 31;
    int lq = l >> 2, lr = l & 3;
    int mw = (wrp >> 1) * 32, nw = (wrp & 1) * 64;

    float4 pA[4], pW[4];
    auto prefetch = [&](int k0) {
#pragma unroll
        for (int v = 0; v < 4; v++) {
            int idx = tid + v*256;
            int m = idx >> 3, kq = idx & 7;
            pA[v] = *(const float4*)&g_normed[(size_t)(bm+m)*CH + k0 + kq*4];
        }
#pragma unroll
        for (int v = 0; v < 4; v++) {
            int idx = tid + v*256;
            int n = idx >> 3, kq = idx & 7;
            pW[v] = *(const float4*)&W[(size_t)(bn+n)*CH + k0 + kq*4];
        }
    };
    auto stage = [&]() {
#pragma unroll
        for (int v = 0; v < 4; v++) {
            int idx = tid + v*256;
            int m = idx >> 3, kq = idx & 7;
            float4 d = pA[v];
            d.x = tf32r(d.x); d.y = tf32r(d.y); d.z = tf32r(d.z); d.w = tf32r(d.w);
            *(float4*)&sA[m*36 + kq*4] = d;
        }
#pragma unroll
        for (int v = 0; v < 4; v++) {
            int idx = tid + v*256;
            int n = idx >> 3, kq = idx & 7;
            float4 d = pW[v];
            sW[(kq*4+0)*136 + n] = tf32r(d.x);
            sW[(kq*4+1)*136 + n] = tf32r(d.y);
            sW[(kq*4+2)*136 + n] = tf32r(d.z);
            sW[(kq*4+3)*136 + n] = tf32r(d.w);
        }
    };

    float acc[2][8][4];
#pragma unroll
    for (int mt = 0; mt < 2; mt++)
#pragma unroll
        for (int nt = 0; nt < 8; nt++)
#pragma unroll
            for (int i = 0; i < 4; i++) acc[mt][nt][i] = 0.f;

    prefetch(0);
    stage();
    __syncthreads();

    for (int it = 0; it < 4; it++) {
        if (it < 3) prefetch((it+1)*32);

#pragma unroll
        for (int ks = 0; ks < 4; ks++) {
            uint32_t a[2][4];
#pragma unroll
            for (int mt = 0; mt < 2; mt++) {
                int r0 = mw + mt*16 + lq;
                a[mt][0] = __float_as_uint(sA[r0*36 + ks*8 + lr]);
                a[mt][1] = __float_as_uint(sA[(r0+8)*36 + ks*8 + lr]);
                a[mt][2] = __float_as_uint(sA[r0*36 + ks*8 + lr + 4]);
                a[mt][3] = __float_as_uint(sA[(r0+8)*36 + ks*8 + lr + 4]);
            }
#pragma unroll
            for (int nt = 0; nt < 8; nt++) {
                uint32_t bb[2];
                bb[0] = __float_as_uint(sW[(ks*8+lr)*136 + nw + nt*8 + lq]);
                bb[1] = __float_as_uint(sW[(ks*8+lr+4)*136 + nw + nt*8 + lq]);
                mma_tf32(acc[0][nt], a[0], bb);
                mma_tf32(acc[1][nt], a[1], bb);
            }
        }
        if (it < 3) {
            __syncthreads();
            stage();
            __syncthreads();
        }
    }

#pragma unroll
    for (int mt = 0; mt < 2; mt++) {
        int row0 = bm + mw + mt*16 + lq;
#pragma unroll
        for (int nt = 0; nt < 8; nt++) {
            int col = bn + nw + nt*8 + lr*2;
            g_zx[(size_t)row0*DINP + col]       = acc[mt][nt][0];
            g_zx[(size_t)row0*DINP + col + 1]   = acc[mt][nt][1];
            g_zx[(size_t)(row0+8)*DINP + col]   = acc[mt][nt][2];
            g_zx[(size_t)(row0+8)*DINP + col+1] = acc[mt][nt][3];
        }
    }
}

// ---------------- 3. causal depthwise conv1d (k=5) + bias + SiLU ----------
__global__ void conv1d_kernel(const float* __restrict__ cw, const float* __restrict__ cb) {
    __shared__ float s[68][128];
    int b = blockIdx.z, ct = blockIdx.y * 128, p0 = blockIdx.x * 64;
    const float* zxb = g_zx + (size_t)b*HW*DINP;
    for (int idx = threadIdx.x; idx < 68*32; idx += 256) {
        int r = idx >> 5, c4 = idx & 31;
        int pos = p0 - 4 + r;
        float4 v = (pos >= 0) ? *(const float4*)&zxb[(size_t)pos*DINP + DI + ct + c4*4]
                              : make_float4(0.f, 0.f, 0.f, 0.f);
        *(float4*)&s[r][c4*4] = v;
    }
    __syncthreads();
    for (int idx = threadIdx.x; idx < 64*128; idx += 256) {
        int r = idx >> 7, c = idx & 127;
        int ch = ct + c;
        float acc = cb[ch];
#pragma unroll
        for (int k = 0; k < 5; k++) acc += s[r+k][c] * cw[ch*5 + k];
        float o = acc / (1.f + expf(-acc));
        g_xbc[((size_t)b*HW + p0 + r)*CC + ch] = o;
    }
}

// ---------------- 4a. SSD chunk kernel — tensor-core GEMMs (U^T form) -----
__global__ void __launch_bounds__(256, 6) ssd_chunk(const float* __restrict__ Alog) {
    __shared__ float sX [Q*72];     // [s][p]  32x64 B-frag (stride 72)
    __shared__ float sBt[64*40];    // [n][s]  64x32; B-frag for M, A-frag for U^T
    __shared__ float sC [Q*68];     // [t][n]  32x64 A-frag for M
    __shared__ float sMw[Q*36];     // [t][s]  32x32 A-frag for y
    __shared__ float sdt[Q], sS[Q], sWU[Q];

    int bid = blockIdx.x;
    int c  = bid & 127;
    int h  = (bid >> 7) & 3;
    int b  = bid >> 9;
    int bh = b*4 + h;
    int pos0 = b*HW + c*Q;
    int tid = threadIdx.x;
    int wrp = tid >> 5, l = tid & 31;
    int lq = l >> 2, lr = l & 3;

#pragma unroll
    for (int v = 0; v < 2; v++) {
        int idx = tid + v*256;
        int s = idx >> 4, n0 = (idx & 15)*4;
        const float* row = g_xbc + (size_t)(pos0+s)*CC;
        float4 xv = *(const float4*)&row[h*HD + n0];
        float4 bv = *(const float4*)&row[DI + n0];
        float4 cv = *(const float4*)&row[DI + DS + n0];
        xv.x = tf32r(xv.x); xv.y = tf32r(xv.y); xv.z = tf32r(xv.z); xv.w = tf32r(xv.w);
        cv.x = tf32r(cv.x); cv.y = tf32r(cv.y); cv.z = tf32r(cv.z); cv.w = tf32r(cv.w);
        *(float4*)&sX[s*72 + n0] = xv;
        *(float4*)&sC[s*68 + n0] = cv;
        sBt[(n0+0)*40 + s] = tf32r(bv.x);
        sBt[(n0+1)*40 + s] = tf32r(bv.y);
        sBt[(n0+2)*40 + s] = tf32r(bv.z);
        sBt[(n0+3)*40 + s] = tf32r(bv.w);
    }
    // warp 0: dt load + parallel prefix scan + wU/P/D
    if (tid < 32) {
        float dtv = g_dt[(size_t)(pos0+tid)*NH + h];
        sdt[tid] = dtv;
        float Ah = -expf(Alog[h]);
        float v = dtv * Ah;
#pragma unroll
        for (int o = 1; o < 32; o <<= 1) {
            float nv = __shfl_up_sync(0xffffffffu, v, o);
            if (tid >= o) v += nv;
        }
        sS[tid] = v;
        float Stot = __shfl_sync(0xffffffffu, v, 31);
        sWU[tid] = expf(Stot - v) * dtv;
        g_P[(size_t)bh*HW + c*Q + tid] = expf(v);
        if (tid == 31) g_D[bh*NCHUNK + c] = expf(Stot);
    }
    __syncthreads();

    // Phase M
    {
        int mt = wrp >> 2, st = wrp & 3;
        float d[4] = {0.f, 0.f, 0.f, 0.f};
#pragma unroll
        for (int ks = 0; ks < 8; ks++) {
            uint32_t a[4], bbr[2];
            const float* Ab = &sC[(mt*16 + lq)*68 + ks*8];
            a[0] = __float_as_uint(Ab[lr]);
            a[1] = __float_as_uint(Ab[8*68 + lr]);
            a[2] = __float_as_uint(Ab[lr + 4]);
            a[3] = __float_as_uint(Ab[8*68 + lr + 4]);
            bbr[0] = __float_as_uint(sBt[(ks*8 + lr)*40 + st*8 + lq]);
            bbr[1] = __float_as_uint(sBt[(ks*8 + lr + 4)*40 + st*8 + lq]);
            mma_tf32(d, a, bbr);
        }
        int t0 = mt*16 + lq, s0 = st*8 + lr*2;
        float st0 = sS[t0], st8 = sS[t0+8];
        float ss0 = sS[s0], ss1 = sS[s0+1];
        float dt0 = sdt[s0], dt1 = sdt[s0+1];
        sMw[t0*36 + s0]       = tf32r((s0   <= t0  ) ? d[0]*expf(st0 - ss0)*dt0 : 0.f);
        sMw[t0*36 + s0+1]     = tf32r((s0+1 <= t0  ) ? d[1]*expf(st0 - ss1)*dt1 : 0.f);
        sMw[(t0+8)*36 + s0]   = tf32r((s0   <= t0+8) ? d[2]*expf(st8 - ss0)*dt0 : 0.f);
        sMw[(t0+8)*36 + s0+1] = tf32r((s0+1 <= t0+8) ? d[3]*expf(st8 - ss1)*dt1 : 0.f);
    }
    __syncthreads();

    // Scale sBt columns by wU[s]
#pragma unroll
    for (int v = 0; v < 2; v++) {
        int idx = tid + v*256;
        int n = idx >> 3, s0 = (idx & 7)*4;
        float4 d = *(const float4*)&sBt[n*40 + s0];
        float4 wu = *(const float4*)&sWU[s0];
        d.x = tf32r(d.x*wu.x); d.y = tf32r(d.y*wu.y);
        d.z = tf32r(d.z*wu.z); d.w = tf32r(d.w*wu.w);
        *(float4*)&sBt[n*40 + s0] = d;
    }
    __syncthreads();

    // Phase y_intra then U^T back-to-back
    {
        float dy[2][4];
#pragma unroll
        for (int mt = 0; mt < 2; mt++)
#pragma unroll
            for (int i = 0; i < 4; i++) dy[mt][i] = 0.f;
#pragma unroll
        for (int ks = 0; ks < 4; ks++) {
            uint32_t bbr[2];
            bbr[0] = __float_as_uint(sX[(ks*8 + lr)*72 + wrp*8 + lq]);
            bbr[1] = __float_as_uint(sX[(ks*8 + lr + 4)*72 + wrp*8 + lq]);
#pragma unroll
            for (int mt = 0; mt < 2; mt++) {
                uint32_t a[4];
                const float* Ab = &sMw[(mt*16 + lq)*36 + ks*8];
                a[0] = __float_as_uint(Ab[lr]);
                a[1] = __float_as_uint(Ab[8*36 + lr]);
                a[2] = __float_as_uint(Ab[lr + 4]);
                a[3] = __float_as_uint(Ab[8*36 + lr + 4]);
                mma_tf32(dy[mt], a, bbr);
            }
        }
        int p0 = wrp*8 + lr*2;
#pragma unroll
        for (int mt = 0; mt < 2; mt++) {
            int t0 = mt*16 + lq;
            float2 v0; v0.x = dy[mt][0]; v0.y = dy[mt][1];
            float2 v1; v1.x = dy[mt][2]; v1.y = dy[mt][3];
            *(float2*)&g_y[(size_t)(pos0 + t0)*DI + h*HD + p0]     = v0;
            *(float2*)&g_y[(size_t)(pos0 + t0 + 8)*DI + h*HD + p0] = v1;
        }
    }
    {
        float du[4][4];
#pragma unroll
        for (int mt = 0; mt < 4; mt++)
#pragma unroll
            for (int i = 0; i < 4; i++) du[mt][i] = 0.f;
#pragma unroll
        for (int ks = 0; ks < 4; ks++) {
            uint32_t bbr[2];
            bbr[0] = __float_as_uint(sX[(ks*8 + lr)*72 + wrp*8 + lq]);
            bbr[1] = __float_as_uint(sX[(ks*8 + lr + 4)*72 + wrp*8 + lq]);
#pragma unroll
            for (int mt = 0; mt < 4; mt++) {
                uint32_t a[4];
                const float* Ab = &sBt[(mt*16 + lq)*40 + ks*8];
                a[0] = __float_as_uint(Ab[lr]);
                a[1] = __float_as_uint(Ab[8*40 + lr]);
                a[2] = __float_as_uint(Ab[lr + 4]);
                a[3] = __float_as_uint(Ab[8*40 + lr + 4]);
                mma_tf32(du[mt], a, bbr);
            }
        }
        float* Uo = g_U + ((size_t)bh*NCHUNK + c)*HD*DS;   // [n][p]
        int p0 = wrp*8 + lr*2;
#pragma unroll
        for (int mt = 0; mt < 4; mt++) {
            int n0 = mt*16 + lq;
            float2 v0; v0.x = du[mt][0]; v0.y = du[mt][1];
            float2 v1; v1.x = du[mt][2]; v1.y = du[mt][3];
            *(float2*)&Uo[n0*64 + p0]       = v0;
            *(float2*)&Uo[(n0+8)*64 + p0]   = v1;
        }
    }
}

// ---------------- 4b. chunk-state recurrence (4-deep prefetch) ------------
__global__ void ssd_chain() {
    int e = blockIdx.x*256 + threadIdx.x;
    int bh = e >> 12, el = e & 4095;
    const float* U = g_U   + (size_t)bh*NCHUNK*4096 + el;
    float*       H = g_hst + (size_t)bh*NCHUNK*4096 + el;
    const float* Dd = g_D + bh*NCHUNK;
    float u[4];
    u[0] = U[0];
    u[1] = U[(size_t)1*4096];
    u[2] = U[(size_t)2*4096];
    u[3] = U[(size_t)3*4096];
    float hval = 0.f;
    for (int ci = 0; ci < NCHUNK; ci++) {
        float uc = u[ci & 3];
        if (ci + 4 < NCHUNK) u[ci & 3] = U[(size_t)(ci+4)*4096];
        H[(size_t)ci*4096] = hval;
        hval = Dd[ci]*hval + uc;
    }
}

// ---------------- 4c. inter-chunk output via tensor cores -----------------
__global__ void __launch_bounds__(256) ssd_inter() {
    __shared__ float sCw[Q*68];     // [t][n] 32x64 A-frag (stride 68)
    __shared__ float sHt[64*72];    // [n][p] 64x64 B-frag (stride 72)
    int bid = blockIdx.x;
    int c  = bid & 127;
    int h  = (bid >> 7) & 3;
    int b  = bid >> 9;
    int bh = b*4 + h;
    int pos0 = b*HW + c*Q;
    int tid = threadIdx.x;
    int wrp = tid >> 5, l = tid & 31;
    int lq = l >> 2, lr = l & 3;

    const float* Hsrc = g_hst + ((size_t)bh*NCHUNK + c)*HD*DS;  // [n][p]
#pragma unroll
    for (int v = 0; v < 4; v++) {
        int idx = tid + v*256;
        int n = idx >> 4, p0 = (idx & 15)*4;
        float4 hv = *(const float4*)&Hsrc[n*64 + p0];
        hv.x = tf32r(hv.x); hv.y = tf32r(hv.y);
        hv.z = tf32r(hv.z); hv.w = tf32r(hv.w);
        *(float4*)&sHt[n*72 + p0] = hv;
    }
#pragma unroll
    for (int v = 0; v < 2; v++) {
        int idx = tid + v*256;
        int t = idx >> 4, n0 = (idx & 15)*4;
        float4 cv = *(const float4*)&g_xbc[(size_t)(pos0+t)*CC + DI + DS + n0];
        float pt = g_P[(size_t)bh*HW + c*Q + t];
        cv.x = tf32r(cv.x*pt); cv.y = tf32r(cv.y*pt);
        cv.z = tf32r(cv.z*pt); cv.w = tf32r(cv.w*pt);
        *(float4*)&sCw[t*68 + n0] = cv;
    }
    __syncthreads();

    float dy[2][4];
#pragma unroll
    for (int mt = 0; mt < 2; mt++)
#pragma unroll
        for (int i = 0; i < 4; i++) dy[mt][i] = 0.f;
#pragma unroll
    for (int ks = 0; ks < 8; ks++) {
        uint32_t bbr[2];
        bbr[0] = __float_as_uint(sHt[(ks*8 + lr)*72 + wrp*8 + lq]);
        bbr[1] = __float_as_uint(sHt[(ks*8 + lr + 4)*72 + wrp*8 + lq]);
#pragma unroll
        for (int mt = 0; mt < 2; mt++) {
            uint32_t a[4];
            const float* Ab = &sCw[(mt*16 + lq)*68 + ks*8];
            a[0] = __float_as_uint(Ab[lr]);
            a[1] = __float_as_uint(Ab[8*68 + lr]);
            a[2] = __float_as_uint(Ab[lr + 4]);
            a[3] = __float_as_uint(Ab[8*68 + lr + 4]);
            mma_tf32(dy[mt], a, bbr);
        }
    }
    int p0 = wrp*8 + lr*2;
#pragma unroll
    for (int mt = 0; mt < 2; mt++) {
        int t0 = mt*16 + lq;
        float* y0 = &g_y[(size_t)(pos0 + t0)*DI + h*HD + p0];
        float* y1 = &g_y[(size_t)(pos0 + t0 + 8)*DI + h*HD + p0];
        float2 c0 = *(float2*)y0; c0.x += dy[mt][0]; c0.y += dy[mt][1]; *(float2*)y0 = c0;
        float2 c1 = *(float2*)y1; c1.x += dy[mt][2]; c1.y += dy[mt][3]; *(float2*)y1 = c1;
    }
}

// ---------------- 5. D-skip + gate(silu(z)) + RMSNorm (float4) ------------
__global__ void gate_kernel(const float* __restrict__ Dsk, const float* __restrict__ rmsw) {
    int warp = threadIdx.x >> 5, lane = threadIdx.x & 31;
    int pos = blockIdx.x * 8 + warp;
    const float4* zrow = (const float4*)(g_zx  + (size_t)pos*DINP);
    const float4* xrow = (const float4*)(g_xbc + (size_t)pos*CC);
    const float4* yrow = (const float4*)(g_y   + (size_t)pos*DI);
    float4 gv[2]; float ss = 0.f;
#pragma unroll
    for (int i = 0; i < 2; i++) {
        int q = lane + 32*i;
        int h = q >> 4;
        float Dh = Dsk[h];
        float4 yv = yrow[q], xv = xrow[q], zv = zrow[q];
        float4 g;
        g.x = (yv.x + Dh*xv.x) * (zv.x / (1.f + expf(-zv.x)));
        g.y = (yv.y + Dh*xv.y) * (zv.y / (1.f + expf(-zv.y)));
        g.z = (yv.z + Dh*xv.z) * (zv.z / (1.f + expf(-zv.z)));
        g.w = (yv.w + Dh*xv.w) * (zv.w / (1.f + expf(-zv.w)));
        gv[i] = g;
        ss += g.x*g.x + g.y*g.y + g.z*g.z + g.w*g.w;
    }
#pragma unroll
    for (int o = 16; o > 0; o >>= 1) ss += __shfl_xor_sync(0xffffffffu, ss, o);
    float sc = rsqrtf(ss*(1.f/256.f) + 1e-5f);
    float4* grow = (float4*)(g_gate + (size_t)pos*DI);
#pragma unroll
    for (int i = 0; i < 2; i++) {
        int q = lane + 32*i;
        const float4 rw = *(const float4*)&rmsw[q*4];
        float4 g = gv[i];
        g.x *= sc*rw.x; g.y *= sc*rw.y; g.z *= sc*rw.z; g.w *= sc*rw.w;
        grow[q] = g;
    }
}

// ---------------- 6. out_proj GEMM (reg double-buffered) + residual -------
__global__ void __launch_bounds__(256) gemm_out_tc(const float* __restrict__ W,
                                                   const float* __restrict__ noisy) {
    __shared__ float sA[128*36];
    __shared__ float sW[32*136];
    int bm = blockIdx.x * 128;
    int tid = threadIdx.x;
    int wrp = tid >> 5, l = tid & 31;
    int lq = l >> 2, lr = l & 3;
    int mw = (wrp >> 1) * 32, nw = (wrp & 1) * 64;

    float4 pA[4], pW[4];
    auto prefetch = [&](int k0) {
#pragma unroll
        for (int v = 0; v < 4; v++) {
            int idx = tid + v*256;
            int m = idx >> 3, kq = idx & 7;
            pA[v] = *(const float4*)&g_gate[(size_t)(bm+m)*DI + k0 + kq*4];
        }
#pragma unroll
        for (int v = 0; v < 4; v++) {
            int idx = tid + v*256;
            int n = idx >> 3, kq = idx & 7;
            pW[v] = *(const float4*)&W[(size_t)n*DI + k0 + kq*4];
        }
    };
    auto stage = [&]() {
#pragma unroll
        for (int v = 0; v < 4; v++) {
            int idx = tid + v*256;
            int m = idx >> 3, kq = idx & 7;
            float4 d = pA[v];
            d.x = tf32r(d.x); d.y = tf32r(d.y); d.z = tf32r(d.z); d.w = tf32r(d.w);
            *(float4*)&sA[m*36 + kq*4] = d;
        }
#pragma unroll
        for (int v = 0; v < 4; v++) {
            int idx = tid + v*256;
            int n = idx >> 3, kq = idx & 7;
            float4 d = pW[v];
            sW[(kq*4+0)*136 + n] = tf32r(d.x);
            sW[(kq*4+1)*136 + n] = tf32r(d.y);
            sW[(kq*4+2)*136 + n] = tf32r(d.z);
            sW[(kq*4+3)*136 + n] = tf32r(d.w);
        }
    };

    float acc[2][8][4];
#pragma unroll
    for (int mt = 0; mt < 2; mt++)
#pragma unroll
        for (int nt = 0; nt < 8; nt++)
#pragma unroll
            for (int i = 0; i < 4; i++) acc[mt][nt][i] = 0.f;

    prefetch(0);
    stage();
    __syncthreads();

    for (int it = 0; it < 8; it++) {
        if (it < 7) prefetch((it+1)*32);

#pragma unroll
        for (int ks = 0; ks < 4; ks++) {
            uint32_t a[2][4];
#pragma unroll
            for (int mt = 0; mt < 2; mt++) {
                int r0 = mw + mt*16 + lq;
                a[mt][0] = __float_as_uint(sA[r0*36 + ks*8 + lr]);
                a[mt][1] = __float_as_uint(sA[(r0+8)*36 + ks*8 + lr]);
                a[mt][2] = __float_as_uint(sA[r0*36 + ks*8 + lr + 4]);
                a[mt][3] = __float_as_uint(sA[(r0+8)*36 + ks*8 + lr + 4]);
            }
#pragma unroll
            for (int nt = 0; nt < 8; nt++) {
                uint32_t bb[2];
                bb[0] = __float_as_uint(sW[(ks*8+lr)*136 + nw + nt*8 + lq]);
                bb[1] = __float_as_uint(sW[(ks*8+lr+4)*136 + nw + nt*8 + lq]);
                mma_tf32(acc[0][nt], a[0], bb);
                mma_tf32(acc[1][nt], a[1], bb);
            }
        }
        if (it < 7) {
            __syncthreads();
            stage();
            __syncthreads();
        }
    }

    // 4-pass m-group transpose epilogue: coalesced (b,c,sp) stores
    float* sT = sA;
    int b = bm >> 12, sp0 = bm & 4095;
    for (int mg = 0; mg < 4; mg++) {
        __syncthreads();
        if ((wrp >> 1) == mg) {
#pragma unroll
            for (int mt = 0; mt < 2; mt++)
#pragma unroll
                for (int nt = 0; nt < 8; nt++) {
                    int cl = nw + nt*8 + lr*2;
                    sT[cl*33 + mt*16 + lq]         = acc[mt][nt][0];
                    sT[(cl+1)*33 + mt*16 + lq]     = acc[mt][nt][1];
                    sT[cl*33 + mt*16 + lq + 8]     = acc[mt][nt][2];
                    sT[(cl+1)*33 + mt*16 + lq + 8] = acc[mt][nt][3];
                }
        }
        __syncthreads();
#pragma unroll
        for (int r = 0; r < 16; r++) {
            int lin = tid + r*256;
            int cch = lin >> 5, mm = lin & 31;
            size_t o = ((size_t)(b*CH + cch))*HW + sp0 + mg*32 + mm;
            g_res[o] = noisy[o] + sT[cch*33 + mm];
        }
    }
}

// ---------------- 7/8. 3x3 conv via tf32 mma, register double-buffer ------
__global__ void __launch_bounds__(256) conv3_tc(const float* __restrict__ in,
                                                const float* __restrict__ w,
                                                const float* __restrict__ bias,
                                                float* __restrict__ out,
                                                const float* __restrict__ resid) {
    __shared__ float sT[6*66*12];     // [r][xx][ci8] pad 12
    __shared__ float sW[9*8*72];      // [tap][ci8][co64 pad 72]

    int b = blockIdx.z, coh = blockIdx.x * 64, y0 = blockIdx.y * 4;
    int tid = threadIdx.x;
    int wrp = tid >> 5, l = tid & 31;
    int yl = wrp >> 1, xh = wrp & 1;
    int lq = l >> 2, lr = l & 3;

    float rIn[13], rW[18];

    auto load_regs = [&](int cc) {
        int ci0 = cc * 8;
#pragma unroll
        for (int k = 0; k < 13; k++) {
            int idx = tid + k*256;
            if (idx < 3168) {
                int xx = idx % 66;
                int t2 = idx / 66;
                int ci = t2 & 7, r = t2 >> 3;
                int iy = y0 - 1 + r; iy = iy < 0 ? -iy : (iy >= 64 ? 126 - iy : iy);
                int ix = xx - 1;     ix = ix < 0 ? -ix : (ix >= 64 ? 126 - ix : ix);
                rIn[k] = in[(((size_t)b*CH + ci0 + ci)*64 + iy)*64 + ix];
            }
        }
#pragma unroll
        for (int k = 0; k < 18; k++) {
            int idx = tid + k*256;
            int co = idx / 72;
            int rem = idx - co*72;
            int ci = rem / 9, kk = rem - ci*9;
            rW[k] = w[((size_t)(coh+co)*CH + ci0 + ci)*9 + kk];
        }
    };
    auto store_regs = [&]() {
#pragma unroll
        for (int k = 0; k < 13; k++) {
            int idx = tid + k*256;
            if (idx < 3168) {
                int xx = idx % 66;
                int t2 = idx / 66;
                int ci = t2 & 7, r = t2 >> 3;
                sT[(r*66 + xx)*12 + ci] = tf32r(rIn[k]);
            }
        }
#pragma unroll
        for (int k = 0; k < 18; k++) {
            int idx = tid + k*256;
            int co = idx / 72;
            int rem = idx - co*72;
            int ci = rem / 9, kk = rem - ci*9;
            sW[(kk*8 + ci)*72 + co] = tf32r(rW[k]);
        }
    };

    float acc[2][8][4];
#pragma unroll
    for (int mt = 0; mt < 2; mt++)
#pragma unroll
        for (int nt = 0; nt < 8; nt++)
#pragma unroll
            for (int i = 0; i < 4; i++) acc[mt][nt][i] = 0.f;

    load_regs(0);
    store_regs();
    __syncthreads();

    for (int cc = 0; cc < 16; cc++) {
        if (cc < 15) load_regs(cc + 1);

#pragma unroll
        for (int kk = 0; kk < 9; kk++) {
            int ky = kk / 3, kx = kk - ky*3;
            uint32_t a[2][4];
#pragma unroll
            for (int mt = 0; mt < 2; mt++) {
                const float* Tb = &sT[((yl + ky)*66 + xh*32 + mt*16 + kx)*12];
                a[mt][0] = __float_as_uint(Tb[lq*12 + lr]);
                a[mt][1] = __float_as_uint(Tb[(lq+8)*12 + lr]);
                a[mt][2] = __float_as_uint(Tb[lq*12 + lr + 4]);
                a[mt][3] = __float_as_uint(Tb[(lq+8)*12 + lr + 4]);
            }
            const float* Wb = &sW[kk*8*72];
#pragma unroll
            for (int nt = 0; nt < 8; nt++) {
                uint32_t bb[2];
                bb[0] = __float_as_uint(Wb[lr*72 + nt*8 + lq]);
                bb[1] = __float_as_uint(Wb[(lr+4)*72 + nt*8 + lq]);
                mma_tf32(acc[0][nt], a[0], bb);
                mma_tf32(acc[1][nt], a[1], bb);
            }
        }
        __syncthreads();
        if (cc < 15) {
            store_regs();
            __syncthreads();
        }
    }

    int y = y0 + yl;
#pragma unroll
    for (int mt = 0; mt < 2; mt++) {
        int x = xh*32 + mt*16 + lq;
#pragma unroll
        for (int nt = 0; nt < 8; nt++) {
            int co = coh + nt*8 + lr*2;
            float b0 = bias[co], b1 = bias[co+1];
            size_t o0 = (((size_t)b*CH + co  )*64 + y)*64 + x;
            size_t o1 = (((size_t)b*CH + co+1)*64 + y)*64 + x;
            float v0 = fmaxf(acc[mt][nt][0] + b0, 0.f);
            float v1 = fmaxf(acc[mt][nt][1] + b1, 0.f);
            float v2 = fmaxf(acc[mt][nt][2] + b0, 0.f);
            float v3 = fmaxf(acc[mt][nt][3] + b1, 0.f);
            if (resid) {
                v0 += resid[o0]; v1 += resid[o1];
                v2 += resid[o0 + 8]; v3 += resid[o1 + 8];
            }
            out[o0] = v0; out[o1] = v1;
            out[o0 + 8] = v2; out[o1 + 8] = v3;
        }
    }
}

// ---------------- launch ---------------------------------------------------
extern "C" void kernel_launch(void* const* d_in, const int* in_sizes, int n_in,
                              void* d_out, int out_size) {
    const float* noisy = (const float*)d_in[0];
    const float* aux   = (const float*)d_in[1];
    const float* gamma = (const float*)d_in[2];
    const float* beta  = (const float*)d_in[3];
    const float* inw   = (const float*)d_in[4];
    const float* cw    = (const float*)d_in[5];
    const float* cb    = (const float*)d_in[6];
    const float* alog  = (const float*)d_in[7];
    const float* dtb   = (const float*)d_in[8];
    const float* Dsk   = (const float*)d_in[9];
    const float* rmsw  = (const float*)d_in[10];
    const float* outw  = (const float*)d_in[11];
    const float* fw1   = (const float*)d_in[12];
    const float* fb1   = (const float*)d_in[13];
    const float* fw2   = (const float*)d_in[14];
    const float* fb2   = (const float*)d_in[15];
    float* out = (float*)d_out;

    void *p_res, *p_ff1;
    cudaGetSymbolAddress(&p_res, g_res);
    cudaGetSymbolAddress(&p_ff1, g_ff1);

    ln_kernel<<<512, 256>>>(noisy, gamma, beta, inw, dtb);
    gemm_in_tc<<<dim3(5, 128), 256>>>(inw);
    conv1d_kernel<<<dim3(64, 3, 4), 256>>>(cw, cb);
    ssd_chunk<<<2048, 256>>>(alog);
    ssd_chain<<<256, 256>>>();
    ssd_inter<<<2048, 256>>>();
    gate_kernel<<<2048, 256>>>(Dsk, rmsw);
    gemm_out_tc<<<128, 256>>>(outw, noisy);
    conv3_tc<<<dim3(2, 16, 4), 256>>>((const float*)p_res, fw1, fb1, (float*)p_ff1, nullptr);
    conv3_tc<<<dim3(2, 16, 4), 256>>>((const float*)p_ff1, fw2, fb2, out, (const float*)p_res);

    // aux passthrough: second half of output
    if (out_size >= 2*LPOS*CH) {
        cudaMemcpyAsync(out + (size_t)LPOS*CH, aux, (size_t)LPOS*CH*sizeof(float),
                        cudaMemcpyDeviceToDevice, 0);
    }
}